// round 6
// baseline (speedup 1.0000x reference)
#include <cuda_runtime.h>

#define N_NODES 20000
#define N_EDGES 200000
#define EDIM 128
#define CE 256                 // C * E_DIM
#define MAXDS 48               // per-side bin capacity (Poisson(5)/side: P(>48) ~ 1e-30)

// Scratch in __device__ globals (zero-initialized at load; g_cnt invariant:
// zero at entry of every kernel_launch call, restored by node_kernel).
__device__ int   g_cnt[N_NODES];              // packed: lo16 = n_left, hi16 = n_right
__device__ int   g_meta_l[N_NODES * MAXDS];   // src indices of left (pos==0) edges
__device__ int   g_meta_r[N_NODES * MAXDS];   // src indices of right (pos==1) edges
__device__ float g_scale[2][EDIM];
__device__ float g_bias[2][EDIM];

// Scatter src indices into per-dst, per-pos bins; 4 edges/thread (int4 loads,
// 4 independent ATOMGs in flight). Block 0 also computes the sigmoid tables
// (consumed only by node_kernel, which launches after us).
__global__ void __launch_bounds__(256) scatter_kernel(
    const int* __restrict__ src, const int* __restrict__ dst,
    const int* __restrict__ pos,
    const float* __restrict__ dl, const float* __restrict__ dr,
    const float* __restrict__ lb, const float* __restrict__ rb)
{
    if (blockIdx.x == 0 && threadIdx.x < EDIM) {
        int e = threadIdx.x;
        g_scale[0][e] = 1.0f / (1.0f + __expf(-dl[e]));
        g_scale[1][e] = 1.0f / (1.0f + __expf(-dr[e]));
        g_bias[0][e]  = lb[e];
        g_bias[1][e]  = rb[e];
    }

    int t = blockIdx.x * blockDim.x + threadIdx.x;
    int e0 = t * 4;
    if (e0 >= N_EDGES) return;   // N_EDGES % 4 == 0, full int4 loads are safe

    int4 s4 = *reinterpret_cast<const int4*>(src + e0);
    int4 d4 = *reinterpret_cast<const int4*>(dst + e0);
    int4 p4 = *reinterpret_cast<const int4*>(pos + e0);

    #pragma unroll
    for (int k = 0; k < 4; k++) {
        int s = (&s4.x)[k];
        int d = (&d4.x)[k];
        bool right = ((&p4.x)[k] != 0);
        int old = atomicAdd(&g_cnt[d], right ? 0x10000 : 1);
        if (right) g_meta_r[d * MAXDS + (old >> 16)]     = s;
        else       g_meta_l[d * MAXDS + (old & 0xFFFF)]  = s;
    }
}

#define ACC4(A, F) do { \
    (A).x += (F).x; (A).y += (F).y; (A).z += (F).z; (A).w += (F).w; } while (0)

// Gather-reduce: 64 threads per node, each owns one float4 of the 256-float row.
// Left/right load chains kept in flight TOGETHER (up to 8 independent LDG.128
// per round). Raw sums only in the loop; scale+bias applied in the epilogue:
// out = (accL*sc0 + accR*sc1 + nl*b0 + nr*b1) / max(nl+nr, 1).
__global__ void __launch_bounds__(256) node_kernel(const float* __restrict__ feat,
                                                   float* __restrict__ out) {
    unsigned tid  = blockIdx.x * blockDim.x + threadIdx.x;
    unsigned node = tid >> 6;               // grid is exactly N_NODES*64 threads
    unsigned chunk = tid & 63u;
    unsigned off   = chunk * 4u;            // 0..252
    unsigned e     = off & (EDIM - 1);      // scale/bias repeat per channel

    int cnt = g_cnt[node];
    int nl = cnt & 0xFFFF;
    int nr = cnt >> 16;

    const int* mpl = &g_meta_l[node * MAXDS];
    const int* mpr = &g_meta_r[node * MAXDS];
    const float* fb = feat + off;

    float4 accL = make_float4(0.f, 0.f, 0.f, 0.f);
    float4 accR = make_float4(0.f, 0.f, 0.f, 0.f);

    int jl = 0, jr = 0;

    // dual 4+4: 8 independent loads in flight
    for (; jl + 4 <= nl && jr + 4 <= nr; jl += 4, jr += 4) {
        int4 ma = *reinterpret_cast<const int4*>(mpl + jl);
        int4 mb = *reinterpret_cast<const int4*>(mpr + jr);
        float4 f0 = *reinterpret_cast<const float4*>(fb + (size_t)ma.x * CE);
        float4 f1 = *reinterpret_cast<const float4*>(fb + (size_t)ma.y * CE);
        float4 f2 = *reinterpret_cast<const float4*>(fb + (size_t)ma.z * CE);
        float4 f3 = *reinterpret_cast<const float4*>(fb + (size_t)ma.w * CE);
        float4 f4 = *reinterpret_cast<const float4*>(fb + (size_t)mb.x * CE);
        float4 f5 = *reinterpret_cast<const float4*>(fb + (size_t)mb.y * CE);
        float4 f6 = *reinterpret_cast<const float4*>(fb + (size_t)mb.z * CE);
        float4 f7 = *reinterpret_cast<const float4*>(fb + (size_t)mb.w * CE);
        ACC4(accL, f0); ACC4(accL, f1); ACC4(accL, f2); ACC4(accL, f3);
        ACC4(accR, f4); ACC4(accR, f5); ACC4(accR, f6); ACC4(accR, f7);
    }
    // remaining 4-wide single-side batches
    for (; jl + 4 <= nl; jl += 4) {
        int4 ma = *reinterpret_cast<const int4*>(mpl + jl);
        float4 f0 = *reinterpret_cast<const float4*>(fb + (size_t)ma.x * CE);
        float4 f1 = *reinterpret_cast<const float4*>(fb + (size_t)ma.y * CE);
        float4 f2 = *reinterpret_cast<const float4*>(fb + (size_t)ma.z * CE);
        float4 f3 = *reinterpret_cast<const float4*>(fb + (size_t)ma.w * CE);
        ACC4(accL, f0); ACC4(accL, f1); ACC4(accL, f2); ACC4(accL, f3);
    }
    for (; jr + 4 <= nr; jr += 4) {
        int4 mb = *reinterpret_cast<const int4*>(mpr + jr);
        float4 f4 = *reinterpret_cast<const float4*>(fb + (size_t)mb.x * CE);
        float4 f5 = *reinterpret_cast<const float4*>(fb + (size_t)mb.y * CE);
        float4 f6 = *reinterpret_cast<const float4*>(fb + (size_t)mb.z * CE);
        float4 f7 = *reinterpret_cast<const float4*>(fb + (size_t)mb.w * CE);
        ACC4(accR, f4); ACC4(accR, f5); ACC4(accR, f6); ACC4(accR, f7);
    }
    // paired scalar tail: 2 loads in flight
    for (; jl < nl && jr < nr; jl++, jr++) {
        float4 f0 = *reinterpret_cast<const float4*>(fb + (size_t)mpl[jl] * CE);
        float4 f1 = *reinterpret_cast<const float4*>(fb + (size_t)mpr[jr] * CE);
        ACC4(accL, f0); ACC4(accR, f1);
    }
    for (; jl < nl; jl++) {
        float4 f0 = *reinterpret_cast<const float4*>(fb + (size_t)mpl[jl] * CE);
        ACC4(accL, f0);
    }
    for (; jr < nr; jr++) {
        float4 f1 = *reinterpret_cast<const float4*>(fb + (size_t)mpr[jr] * CE);
        ACC4(accR, f1);
    }

    // epilogue: scale + bias + mean
    float4 sc0 = *reinterpret_cast<const float4*>(&g_scale[0][e]);
    float4 sc1 = *reinterpret_cast<const float4*>(&g_scale[1][e]);
    float4 b0  = *reinterpret_cast<const float4*>(&g_bias[0][e]);
    float4 b1  = *reinterpret_cast<const float4*>(&g_bias[1][e]);
    float fnl = (float)nl, fnr = (float)nr;
    float inv = 1.0f / fmaxf(fnl + fnr, 1.0f);

    float4 r;
    r.x = (accL.x * sc0.x + accR.x * sc1.x + fnl * b0.x + fnr * b1.x) * inv;
    r.y = (accL.y * sc0.y + accR.y * sc1.y + fnl * b0.y + fnr * b1.y) * inv;
    r.z = (accL.z * sc0.z + accR.z * sc1.z + fnl * b0.z + fnr * b1.z) * inv;
    r.w = (accL.w * sc0.w + accR.w * sc1.w + fnl * b0.w + fnr * b1.w) * inv;
    *reinterpret_cast<float4*>(out + (size_t)node * CE + off) = r;

    // Restore g_cnt = 0 for the next graph replay. Barrier ensures both warps
    // of every node in this block have read g_cnt before any reset.
    __syncthreads();
    if (chunk == 0) g_cnt[node] = 0;
}

extern "C" void kernel_launch(void* const* d_in, const int* in_sizes, int n_in,
                              void* d_out, int out_size) {
    const float* feat = (const float*)d_in[0];
    const float* dl   = (const float*)d_in[1];
    const float* dr   = (const float*)d_in[2];
    const float* lb   = (const float*)d_in[3];
    const float* rb   = (const float*)d_in[4];
    const int*   src  = (const int*)d_in[5];
    const int*   dst  = (const int*)d_in[6];
    const int*   pos  = (const int*)d_in[7];
    float* out = (float*)d_out;

    scatter_kernel<<<(N_EDGES / 4 + 255) / 256, 256>>>(src, dst, pos, dl, dr, lb, rb);
    node_kernel<<<N_NODES * 64 / 256, 256>>>(feat, out);
}